// round 15
// baseline (speedup 1.0000x reference)
#include <cuda_runtime.h>

#define NN 50000
#define NE 800000
#define F1 128
#define F2 64
#define NB ((NN + 255) / 256)   // 196 scan blocks

typedef unsigned long long u64t;

// ---------------- packed f32x2 helpers ----------------
__device__ __forceinline__ u64t pack2(float a, float b) {
    u64t r; asm("mov.b64 %0,{%1,%2};" : "=l"(r) : "f"(a), "f"(b)); return r;
}
__device__ __forceinline__ float2 unpack2(u64t v) {
    float2 r; asm("mov.b64 {%0,%1},%2;" : "=f"(r.x), "=f"(r.y) : "l"(v)); return r;
}
__device__ __forceinline__ void ffma2(u64t& d, u64t a, u64t b) {
    asm("fma.rn.f32x2 %0,%1,%2,%0;" : "+l"(d) : "l"(a), "l"(b));
}
__device__ __forceinline__ void fadd2(u64t& d, u64t a) {
    asm("add.rn.f32x2 %0,%0,%1;" : "+l"(d) : "l"(a));
}
__device__ __forceinline__ float hsum2(u64t v) {
    float2 f = unpack2(v); return f.x + f.y;
}

// ---------------- scratch (zero-initialized at load; deg re-zeroed by layer2 tail) ----------------
__device__ int   g_degout[NN];
__device__ int   g_degin[NN];
__device__ float g_sout[NN];
__device__ float g_sin[NN];
__device__ int   g_part[256];
__device__ int   g_rowstart[NN + 1];
__device__ int   g_cursor[NN];
__device__ int   g_csrc[NE];
__device__ float g_agg1[NN * F1];
__device__ float g_h2[NN * F2];

// ---------------- degree ----------------
__global__ void k_deg(const int4* __restrict__ src4, const int4* __restrict__ dst4) {
    int i = blockIdx.x * blockDim.x + threadIdx.x;
    if (i < NE / 4) {
        int4 s = src4[i], d = dst4[i];
        atomicAdd(&g_degout[s.x], 1); atomicAdd(&g_degout[s.y], 1);
        atomicAdd(&g_degout[s.z], 1); atomicAdd(&g_degout[s.w], 1);
        atomicAdd(&g_degin[d.x], 1);  atomicAdd(&g_degin[d.y], 1);
        atomicAdd(&g_degin[d.z], 1);  atomicAdd(&g_degin[d.w], 1);
    }
}

// ---------------- scan (3 kernels — multi-block, proven) ----------------
__global__ void k_scan1() {
    __shared__ int sh[256];
    int i = blockIdx.x * 256 + threadIdx.x;
    int din = 0;
    if (i < NN) {
        din = g_degin[i];
        g_sout[i] = rsqrtf(fmaxf((float)g_degout[i], 1.0f));
        g_sin[i]  = rsqrtf(fmaxf((float)din, 1.0f));
    }
    sh[threadIdx.x] = din;
    __syncthreads();
    for (int s = 128; s > 0; s >>= 1) {
        if (threadIdx.x < s) sh[threadIdx.x] += sh[threadIdx.x + s];
        __syncthreads();
    }
    if (threadIdx.x == 0) g_part[blockIdx.x] = sh[0];
}

__global__ void k_scan2() {
    __shared__ int sh[256];
    int t = threadIdx.x;
    int v = (t < NB) ? g_part[t] : 0;
    sh[t] = v;
    __syncthreads();
    for (int off = 1; off < 256; off <<= 1) {
        int x = (t >= off) ? sh[t - off] : 0;
        __syncthreads();
        sh[t] += x;
        __syncthreads();
    }
    g_part[t] = sh[t] - v;
    if (t == 255) g_rowstart[NN] = sh[255];
}

__global__ void k_scan3() {
    __shared__ int sh[256];
    int t = threadIdx.x;
    int i = blockIdx.x * 256 + t;
    int v = (i < NN) ? g_degin[i] : 0;
    sh[t] = v;
    __syncthreads();
    for (int off = 1; off < 256; off <<= 1) {
        int x = (t >= off) ? sh[t - off] : 0;
        __syncthreads();
        sh[t] += x;
        __syncthreads();
    }
    if (i < NN) {
        g_rowstart[i] = g_part[blockIdx.x] + sh[t] - v;
        g_cursor[i] = 0;
    }
}

__global__ void k_fill(const int4* __restrict__ src4, const int4* __restrict__ dst4) {
    int i = blockIdx.x * blockDim.x + threadIdx.x;
    if (i < NE / 4) {
        int4 s = src4[i], d = dst4[i];
        int p;
        p = atomicAdd(&g_cursor[d.x], 1); g_csrc[g_rowstart[d.x] + p] = s.x;
        p = atomicAdd(&g_cursor[d.y], 1); g_csrc[g_rowstart[d.y] + p] = s.y;
        p = atomicAdd(&g_cursor[d.z], 1); g_csrc[g_rowstart[d.z] + p] = s.z;
        p = atomicAdd(&g_cursor[d.w], 1); g_csrc[g_rowstart[d.w] + p] = s.w;
    }
}

// ---------------- gather1: one warp per node, no smem, high occupancy ----------------
__global__ __launch_bounds__(256)
void k_gather(const float* __restrict__ featp) {
    int warp = (blockIdx.x * blockDim.x + threadIdx.x) >> 5;
    int lane = threadIdx.x & 31;
    if (warp >= NN) return;
    int r = warp;

    const longlong2* feat2 = (const longlong2*)featp;
    u64t acc0 = 0, acc1 = 0;
    int beg = __ldg(&g_rowstart[r]), end = __ldg(&g_rowstart[r + 1]);
    for (int j = beg; j < end; j += 32) {
        int n = min(32, end - j);
        int sid = 0; float sv = 0.f;
        if (lane < n) { sid = g_csrc[j + lane]; sv = g_sout[sid]; }
        int kk = 0;
        for (; kk + 8 <= n; kk += 8) {
            longlong2 f[8]; u64t sp[8];
            #pragma unroll
            for (int q = 0; q < 8; q++) {
                int   s  = __shfl_sync(0xffffffffu, sid, kk + q);
                float sc = __shfl_sync(0xffffffffu, sv, kk + q);
                f[q] = feat2[s * 32 + lane];
                sp[q] = pack2(sc, sc);
            }
            #pragma unroll
            for (int q = 0; q < 8; q++) {
                ffma2(acc0, sp[q], (u64t)f[q].x);
                ffma2(acc1, sp[q], (u64t)f[q].y);
            }
        }
        for (; kk < n; kk++) {
            int   s  = __shfl_sync(0xffffffffu, sid, kk);
            float sc = __shfl_sync(0xffffffffu, sv, kk);
            longlong2 f = feat2[s * 32 + lane];
            u64t sp = pack2(sc, sc);
            ffma2(acc0, sp, (u64t)f.x);
            ffma2(acc1, sp, (u64t)f.y);
        }
    }
    float2 a0 = unpack2(acc0), a1 = unpack2(acc1);
    ((float4*)g_agg1)[r * 32 + lane] = make_float4(a0.x, a0.y, a1.x, a1.y);
}

// ---------------- double GEMM with k-paired FFMA2 (no pack MOVs in inner loops) ----------------
// smem weights stored k-interleaved: wp[k2*C + c] = (W[2k2][c], W[2k2+1][c]).
// acc2 accumulates (even-k sum, odd-k sum); final = .lo + .hi.
#define RPB 64  // 8 warps * 4 rows * 2 passes

__global__ __launch_bounds__(256, 2)
void k_gemm(const float* __restrict__ W1f, const float* __restrict__ W2f,
            const float* __restrict__ b1g) {
    extern __shared__ float sm[];
    u64t* sW1p = (u64t*)sm;                  // 8192 u64 = 64KB
    u64t* sW2p = sW1p + (F1 / 2) * F1;       // 4096 u64 = 32KB
    float* sBuf = (float*)(sW2p + (F1 / 2) * F2);  // 8 warps * 512 floats = 16KB

    int tid = threadIdx.x;
    // interleaved W1: idx -> (k2, c)
    for (int idx = tid; idx < (F1 / 2) * F1; idx += 256) {
        int k2 = idx >> 7, c = idx & 127;
        sW1p[idx] = pack2(W1f[(2 * k2) * F1 + c], W1f[(2 * k2 + 1) * F1 + c]);
    }
    // interleaved W2
    for (int idx = tid; idx < (F1 / 2) * F2; idx += 256) {
        int k2 = idx >> 6, c = idx & 63;
        sW2p[idx] = pack2(W2f[(2 * k2) * F2 + c], W2f[(2 * k2 + 1) * F2 + c]);
    }
    __syncthreads();

    int w = tid >> 5, lane = tid & 31;
    float* myBuf = sBuf + w * 512;
    float4 b1v = ((const float4*)b1g)[lane];
    const longlong2* w1v = (const longlong2*)sW1p;
    const longlong2* w2v = (const longlong2*)sW2p;

    for (int pass = 0; pass < 2; pass++) {
        int r0 = blockIdx.x * RPB + pass * 32 + w * 4;

        // stream 4 agg rows into per-warp smem buffer
        #pragma unroll
        for (int i = 0; i < 4; i++) {
            int r = r0 + i;
            float4 a = (r < NN) ? __ldg(&((const float4*)g_agg1)[r * 32 + lane])
                                : make_float4(0.f, 0.f, 0.f, 0.f);
            ((float4*)myBuf)[i * 32 + lane] = a;
        }
        __syncwarp();

        // ---- GEMM1: 4 rows x 4 cols, k-paired ----
        u64t A00 = 0, A01 = 0, A02 = 0, A03 = 0;
        u64t A10 = 0, A11 = 0, A12 = 0, A13 = 0;
        u64t A20 = 0, A21 = 0, A22 = 0, A23 = 0;
        u64t A30 = 0, A31 = 0, A32 = 0, A33 = 0;
        const u64t* bufp = (const u64t*)myBuf;
        #pragma unroll 4
        for (int k2 = 0; k2 < F1 / 2; k2++) {
            longlong2 wA = w1v[k2 * 64 + 2 * lane];       // cols 4lane, 4lane+1
            longlong2 wB = w1v[k2 * 64 + 2 * lane + 1];   // cols 4lane+2, 4lane+3
            u64t a0 = bufp[0 * 64 + k2], a1 = bufp[1 * 64 + k2];
            u64t a2 = bufp[2 * 64 + k2], a3 = bufp[3 * 64 + k2];
            ffma2(A00, a0, (u64t)wA.x); ffma2(A01, a0, (u64t)wA.y);
            ffma2(A02, a0, (u64t)wB.x); ffma2(A03, a0, (u64t)wB.y);
            ffma2(A10, a1, (u64t)wA.x); ffma2(A11, a1, (u64t)wA.y);
            ffma2(A12, a1, (u64t)wB.x); ffma2(A13, a1, (u64t)wB.y);
            ffma2(A20, a2, (u64t)wA.x); ffma2(A21, a2, (u64t)wA.y);
            ffma2(A22, a2, (u64t)wB.x); ffma2(A23, a2, (u64t)wB.y);
            ffma2(A30, a3, (u64t)wA.x); ffma2(A31, a3, (u64t)wA.y);
            ffma2(A32, a3, (u64t)wB.x); ffma2(A33, a3, (u64t)wB.y);
        }
        __syncwarp();

        // ---- epilogue1: v = relu(sum*s_in + b1) * s_out ----
        #pragma unroll
        for (int i = 0; i < 4; i++) {
            int r = r0 + i;
            float si = (r < NN) ? g_sin[r] : 1.0f;
            float so = (r < NN) ? g_sout[r] : 0.0f;
            float s0, s1, s2, s3;
            if (i == 0) { s0 = hsum2(A00); s1 = hsum2(A01); s2 = hsum2(A02); s3 = hsum2(A03); }
            else if (i == 1) { s0 = hsum2(A10); s1 = hsum2(A11); s2 = hsum2(A12); s3 = hsum2(A13); }
            else if (i == 2) { s0 = hsum2(A20); s1 = hsum2(A21); s2 = hsum2(A22); s3 = hsum2(A23); }
            else { s0 = hsum2(A30); s1 = hsum2(A31); s2 = hsum2(A32); s3 = hsum2(A33); }
            float4 v;
            v.x = fmaxf(fmaf(s0, si, b1v.x), 0.f) * so;
            v.y = fmaxf(fmaf(s1, si, b1v.y), 0.f) * so;
            v.z = fmaxf(fmaf(s2, si, b1v.z), 0.f) * so;
            v.w = fmaxf(fmaf(s3, si, b1v.w), 0.f) * so;
            ((float4*)myBuf)[i * 32 + lane] = v;
        }
        __syncwarp();

        // ---- GEMM2: 4 rows x 2 cols, k-paired ----
        u64t C00 = 0, C01 = 0, C10 = 0, C11 = 0;
        u64t C20 = 0, C21 = 0, C30 = 0, C31 = 0;
        #pragma unroll 4
        for (int k2 = 0; k2 < F1 / 2; k2++) {
            longlong2 wv = w2v[k2 * 32 + lane];   // cols 2lane, 2lane+1
            u64t a0 = bufp[0 * 64 + k2], a1 = bufp[1 * 64 + k2];
            u64t a2 = bufp[2 * 64 + k2], a3 = bufp[3 * 64 + k2];
            ffma2(C00, a0, (u64t)wv.x); ffma2(C01, a0, (u64t)wv.y);
            ffma2(C10, a1, (u64t)wv.x); ffma2(C11, a1, (u64t)wv.y);
            ffma2(C20, a2, (u64t)wv.x); ffma2(C21, a2, (u64t)wv.y);
            ffma2(C30, a3, (u64t)wv.x); ffma2(C31, a3, (u64t)wv.y);
        }

        #pragma unroll
        for (int i = 0; i < 4; i++) {
            int r = r0 + i;
            if (r < NN) {
                float2 c;
                if (i == 0) { c = make_float2(hsum2(C00), hsum2(C01)); }
                else if (i == 1) { c = make_float2(hsum2(C10), hsum2(C11)); }
                else if (i == 2) { c = make_float2(hsum2(C20), hsum2(C21)); }
                else { c = make_float2(hsum2(C30), hsum2(C31)); }
                ((float2*)g_h2)[r * 32 + lane] = c;
            }
        }
        __syncwarp();
    }
}

// ---------------- fused: gather2 + bias + log_softmax (+ zero deg for next replay) ----------------
__global__ void k_layer2(float* __restrict__ out, const float* __restrict__ b2) {
    int t = blockIdx.x * blockDim.x + threadIdx.x;

    // tail duty: re-zero degree arrays for the next replay (first call sees static zeros)
    if (t < NN / 4) {
        ((int4*)g_degout)[t] = make_int4(0, 0, 0, 0);
        ((int4*)g_degin)[t]  = make_int4(0, 0, 0, 0);
    }

    int warp = t >> 5;
    int lane = threadIdx.x & 31;
    int g = lane >> 4;
    int sub = lane & 15;
    int r = warp * 2 + g;
    if (r >= NN) return;
    unsigned gmask = 0xFFFFu << (g * 16);

    int beg = __ldg(&g_rowstart[r]), end = __ldg(&g_rowstart[r + 1]);
    u64t acc0 = 0, acc1 = 0;
    const longlong2* h2v = (const longlong2*)g_h2;
    for (int j = beg; j < end; j += 16) {
        int n = min(16, end - j);
        int sid = (sub < n) ? g_csrc[j + sub] : 0;
        int kk = 0;
        for (; kk + 4 <= n; kk += 4) {
            longlong2 f[4];
            #pragma unroll
            for (int q = 0; q < 4; q++) {
                int s = __shfl_sync(gmask, sid, kk + q, 16);
                f[q] = h2v[s * 16 + sub];
            }
            #pragma unroll
            for (int q = 0; q < 4; q++) {
                fadd2(acc0, (u64t)f[q].x);
                fadd2(acc1, (u64t)f[q].y);
            }
        }
        for (; kk < n; kk++) {
            int s = __shfl_sync(gmask, sid, kk, 16);
            longlong2 f = h2v[s * 16 + sub];
            fadd2(acc0, (u64t)f.x);
            fadd2(acc1, (u64t)f.y);
        }
    }

    float si = g_sin[r];
    float2 a0 = unpack2(acc0), a1 = unpack2(acc1);
    float4 b = ((const float4*)b2)[sub];
    float y0 = fmaf(a0.x, si, b.x);
    float y1 = fmaf(a0.y, si, b.y);
    float y2 = fmaf(a1.x, si, b.z);
    float y3 = fmaf(a1.y, si, b.w);

    float m = fmaxf(fmaxf(y0, y1), fmaxf(y2, y3));
    #pragma unroll
    for (int off = 8; off > 0; off >>= 1)
        m = fmaxf(m, __shfl_xor_sync(gmask, m, off, 16));
    float ssum = expf(y0 - m) + expf(y1 - m) + expf(y2 - m) + expf(y3 - m);
    #pragma unroll
    for (int off = 8; off > 0; off >>= 1)
        ssum += __shfl_xor_sync(gmask, ssum, off, 16);
    float l = m + logf(ssum);

    ((float4*)out)[r * 16 + sub] = make_float4(y0 - l, y1 - l, y2 - l, y3 - l);
}

// ---------------- launch ----------------
extern "C" void kernel_launch(void* const* d_in, const int* in_sizes, int n_in,
                              void* d_out, int out_size) {
    const float* feat = (const float*)d_in[0];
    const int*   src  = (const int*)d_in[1];
    const int*   dst  = (const int*)d_in[2];
    const float* W1   = (const float*)d_in[3];
    const float* b1   = (const float*)d_in[4];
    const float* W2   = (const float*)d_in[5];
    const float* b2   = (const float*)d_in[6];
    float* out = (float*)d_out;

    (void)in_sizes; (void)n_in; (void)out_size;

    static bool attr_done = false;
    const int smem_bytes = (F1 * F1 + F1 * F2 + 8 * 4 * F1) * (int)sizeof(float); // 114688
    if (!attr_done) {
        cudaFuncSetAttribute(k_gemm, cudaFuncAttributeMaxDynamicSharedMemorySize, smem_bytes);
        attr_done = true;
    }

    k_deg<<<(NE / 4 + 255) / 256, 256>>>((const int4*)src, (const int4*)dst);
    k_scan1<<<NB, 256>>>();
    k_scan2<<<1, 256>>>();
    k_scan3<<<NB, 256>>>();
    k_fill<<<(NE / 4 + 255) / 256, 256>>>((const int4*)src, (const int4*)dst);
    k_gather<<<(NN * 32 + 255) / 256, 256>>>(feat);
    k_gemm<<<(NN + RPB - 1) / RPB, 256, smem_bytes>>>(W1, W2, b1);
    k_layer2<<<(NN / 2 * 32 + 255) / 256, 256>>>(out, b2);
}

// round 16
// speedup vs baseline: 1.1174x; 1.1174x over previous
#include <cuda_runtime.h>

#define NN 50000
#define NE 800000
#define F1 128
#define F2 64
#define NB ((NN + 255) / 256)   // 196 scan blocks

typedef unsigned long long u64t;

// ---------------- packed f32x2 helpers ----------------
__device__ __forceinline__ u64t pack2(float a, float b) {
    u64t r; asm("mov.b64 %0,{%1,%2};" : "=l"(r) : "f"(a), "f"(b)); return r;
}
__device__ __forceinline__ float2 unpack2(u64t v) {
    float2 r; asm("mov.b64 {%0,%1},%2;" : "=f"(r.x), "=f"(r.y) : "l"(v)); return r;
}
__device__ __forceinline__ void ffma2(u64t& d, u64t a, u64t b) {
    asm("fma.rn.f32x2 %0,%1,%2,%0;" : "+l"(d) : "l"(a), "l"(b));
}
__device__ __forceinline__ void fadd2(u64t& d, u64t a) {
    asm("add.rn.f32x2 %0,%0,%1;" : "+l"(d) : "l"(a));
}
__device__ __forceinline__ float hsum2(u64t v) {
    float2 f = unpack2(v); return f.x + f.y;
}

// ---------------- scratch (zero-initialized at load; deg re-zeroed by layer2 tail) ----------------
__device__ int   g_degout[NN];
__device__ int   g_degin[NN];
__device__ float g_sout[NN];
__device__ float g_sin[NN];
__device__ int   g_part[256];
__device__ int   g_rowstart[NN + 1];
__device__ int   g_cursor[NN];
__device__ int   g_csrc[NE];
__device__ float g_agg1[NN * F1];
__device__ float g_h2[NN * F2];

// ---------------- degree ----------------
__global__ void k_deg(const int4* __restrict__ src4, const int4* __restrict__ dst4) {
    int i = blockIdx.x * blockDim.x + threadIdx.x;
    if (i < NE / 4) {
        int4 s = src4[i], d = dst4[i];
        atomicAdd(&g_degout[s.x], 1); atomicAdd(&g_degout[s.y], 1);
        atomicAdd(&g_degout[s.z], 1); atomicAdd(&g_degout[s.w], 1);
        atomicAdd(&g_degin[d.x], 1);  atomicAdd(&g_degin[d.y], 1);
        atomicAdd(&g_degin[d.z], 1);  atomicAdd(&g_degin[d.w], 1);
    }
}

// ---------------- scan (3 kernels — multi-block, proven) ----------------
__global__ void k_scan1() {
    __shared__ int sh[256];
    int i = blockIdx.x * 256 + threadIdx.x;
    int din = 0;
    if (i < NN) {
        din = g_degin[i];
        g_sout[i] = rsqrtf(fmaxf((float)g_degout[i], 1.0f));
        g_sin[i]  = rsqrtf(fmaxf((float)din, 1.0f));
    }
    sh[threadIdx.x] = din;
    __syncthreads();
    for (int s = 128; s > 0; s >>= 1) {
        if (threadIdx.x < s) sh[threadIdx.x] += sh[threadIdx.x + s];
        __syncthreads();
    }
    if (threadIdx.x == 0) g_part[blockIdx.x] = sh[0];
}

__global__ void k_scan2() {
    __shared__ int sh[256];
    int t = threadIdx.x;
    int v = (t < NB) ? g_part[t] : 0;
    sh[t] = v;
    __syncthreads();
    for (int off = 1; off < 256; off <<= 1) {
        int x = (t >= off) ? sh[t - off] : 0;
        __syncthreads();
        sh[t] += x;
        __syncthreads();
    }
    g_part[t] = sh[t] - v;
    if (t == 255) g_rowstart[NN] = sh[255];
}

__global__ void k_scan3() {
    __shared__ int sh[256];
    int t = threadIdx.x;
    int i = blockIdx.x * 256 + t;
    int v = (i < NN) ? g_degin[i] : 0;
    sh[t] = v;
    __syncthreads();
    for (int off = 1; off < 256; off <<= 1) {
        int x = (t >= off) ? sh[t - off] : 0;
        __syncthreads();
        sh[t] += x;
        __syncthreads();
    }
    if (i < NN) {
        g_rowstart[i] = g_part[blockIdx.x] + sh[t] - v;
        g_cursor[i] = 0;
    }
}

__global__ void k_fill(const int4* __restrict__ src4, const int4* __restrict__ dst4) {
    int i = blockIdx.x * blockDim.x + threadIdx.x;
    if (i < NE / 4) {
        int4 s = src4[i], d = dst4[i];
        int p;
        p = atomicAdd(&g_cursor[d.x], 1); g_csrc[g_rowstart[d.x] + p] = s.x;
        p = atomicAdd(&g_cursor[d.y], 1); g_csrc[g_rowstart[d.y] + p] = s.y;
        p = atomicAdd(&g_cursor[d.z], 1); g_csrc[g_rowstart[d.z] + p] = s.z;
        p = atomicAdd(&g_cursor[d.w], 1); g_csrc[g_rowstart[d.w] + p] = s.w;
    }
}

// ---------------- gather1: one warp per node, no smem, high occupancy ----------------
__global__ __launch_bounds__(256)
void k_gather(const float* __restrict__ featp) {
    int warp = (blockIdx.x * blockDim.x + threadIdx.x) >> 5;
    int lane = threadIdx.x & 31;
    if (warp >= NN) return;
    int r = warp;

    const longlong2* feat2 = (const longlong2*)featp;
    u64t acc0 = 0, acc1 = 0;
    int beg = __ldg(&g_rowstart[r]), end = __ldg(&g_rowstart[r + 1]);
    for (int j = beg; j < end; j += 32) {
        int n = min(32, end - j);
        int sid = 0; float sv = 0.f;
        if (lane < n) { sid = g_csrc[j + lane]; sv = g_sout[sid]; }
        int kk = 0;
        for (; kk + 8 <= n; kk += 8) {
            longlong2 f[8]; u64t sp[8];
            #pragma unroll
            for (int q = 0; q < 8; q++) {
                int   s  = __shfl_sync(0xffffffffu, sid, kk + q);
                float sc = __shfl_sync(0xffffffffu, sv, kk + q);
                f[q] = feat2[s * 32 + lane];
                sp[q] = pack2(sc, sc);
            }
            #pragma unroll
            for (int q = 0; q < 8; q++) {
                ffma2(acc0, sp[q], (u64t)f[q].x);
                ffma2(acc1, sp[q], (u64t)f[q].y);
            }
        }
        for (; kk < n; kk++) {
            int   s  = __shfl_sync(0xffffffffu, sid, kk);
            float sc = __shfl_sync(0xffffffffu, sv, kk);
            longlong2 f = feat2[s * 32 + lane];
            u64t sp = pack2(sc, sc);
            ffma2(acc0, sp, (u64t)f.x);
            ffma2(acc1, sp, (u64t)f.y);
        }
    }
    float2 a0 = unpack2(acc0), a1 = unpack2(acc1);
    ((float4*)g_agg1)[r * 32 + lane] = make_float4(a0.x, a0.y, a1.x, a1.y);
}

// ---------------- double GEMM: k-paired FFMA2, conflict-free dual-array weights ----------------
// sW1A[k2*32+l] = ((W[2k2][4l],W[2k2+1][4l]), (W[2k2][4l+1],W[2k2+1][4l+1]))   16B/lane stride
// sW1B[k2*32+l] = same for cols 4l+2, 4l+3
// sW2 [k2*32+l] = pairs for cols 2l, 2l+1
#define RPB 64  // 8 warps * 4 rows * 2 passes

__global__ __launch_bounds__(256, 2)
void k_gemm(const float* __restrict__ W1f, const float* __restrict__ W2f,
            const float* __restrict__ b1g) {
    extern __shared__ float sm[];
    u64t* sW1A = (u64t*)sm;                  // 4096 u64 = 32KB
    u64t* sW1B = sW1A + 4096;                // 32KB
    u64t* sW2p = sW1B + 4096;                // 32KB
    float* sBuf = (float*)(sW2p + 4096);     // 8 warps * 512 floats = 16KB

    int tid = threadIdx.x;
    // fill W1 pair arrays: idx -> (k2, l)
    for (int idx = tid; idx < 64 * 32; idx += 256) {
        int k2 = idx >> 5, l = idx & 31;
        const float* r0 = W1f + (2 * k2) * F1;
        const float* r1 = W1f + (2 * k2 + 1) * F1;
        int c = 4 * l;
        longlong2 vA, vB;
        vA.x = (long long)pack2(r0[c],     r1[c]);
        vA.y = (long long)pack2(r0[c + 1], r1[c + 1]);
        vB.x = (long long)pack2(r0[c + 2], r1[c + 2]);
        vB.y = (long long)pack2(r0[c + 3], r1[c + 3]);
        ((longlong2*)sW1A)[idx] = vA;
        ((longlong2*)sW1B)[idx] = vB;
    }
    // fill W2 pair array
    for (int idx = tid; idx < 64 * 32; idx += 256) {
        int k2 = idx >> 5, l = idx & 31;
        const float* r0 = W2f + (2 * k2) * F2;
        const float* r1 = W2f + (2 * k2 + 1) * F2;
        longlong2 v;
        v.x = (long long)pack2(r0[2 * l],     r1[2 * l]);
        v.y = (long long)pack2(r0[2 * l + 1], r1[2 * l + 1]);
        ((longlong2*)sW2p)[idx] = v;
    }
    __syncthreads();

    int w = tid >> 5, lane = tid & 31;
    float* myBuf = sBuf + w * 512;
    float4 b1v = ((const float4*)b1g)[lane];
    const longlong2* w1a = (const longlong2*)sW1A;
    const longlong2* w1b = (const longlong2*)sW1B;
    const longlong2* w2v = (const longlong2*)sW2p;

    for (int pass = 0; pass < 2; pass++) {
        int r0 = blockIdx.x * RPB + pass * 32 + w * 4;

        // stream 4 agg rows into per-warp smem buffer
        #pragma unroll
        for (int i = 0; i < 4; i++) {
            int r = r0 + i;
            float4 a = (r < NN) ? __ldg(&((const float4*)g_agg1)[r * 32 + lane])
                                : make_float4(0.f, 0.f, 0.f, 0.f);
            ((float4*)myBuf)[i * 32 + lane] = a;
        }
        __syncwarp();

        // ---- GEMM1: 4 rows x 4 cols, k-paired, conflict-free ----
        u64t A00 = 0, A01 = 0, A02 = 0, A03 = 0;
        u64t A10 = 0, A11 = 0, A12 = 0, A13 = 0;
        u64t A20 = 0, A21 = 0, A22 = 0, A23 = 0;
        u64t A30 = 0, A31 = 0, A32 = 0, A33 = 0;
        const u64t* bufp = (const u64t*)myBuf;
        #pragma unroll 4
        for (int k2 = 0; k2 < F1 / 2; k2++) {
            longlong2 wA = w1a[k2 * 32 + lane];   // cols 4l, 4l+1
            longlong2 wB = w1b[k2 * 32 + lane];   // cols 4l+2, 4l+3
            u64t a0 = bufp[0 * 64 + k2], a1 = bufp[1 * 64 + k2];
            u64t a2 = bufp[2 * 64 + k2], a3 = bufp[3 * 64 + k2];
            ffma2(A00, a0, (u64t)wA.x); ffma2(A01, a0, (u64t)wA.y);
            ffma2(A02, a0, (u64t)wB.x); ffma2(A03, a0, (u64t)wB.y);
            ffma2(A10, a1, (u64t)wA.x); ffma2(A11, a1, (u64t)wA.y);
            ffma2(A12, a1, (u64t)wB.x); ffma2(A13, a1, (u64t)wB.y);
            ffma2(A20, a2, (u64t)wA.x); ffma2(A21, a2, (u64t)wA.y);
            ffma2(A22, a2, (u64t)wB.x); ffma2(A23, a2, (u64t)wB.y);
            ffma2(A30, a3, (u64t)wA.x); ffma2(A31, a3, (u64t)wA.y);
            ffma2(A32, a3, (u64t)wB.x); ffma2(A33, a3, (u64t)wB.y);
        }
        __syncwarp();

        // ---- epilogue1: v = relu(sum*s_in + b1) * s_out ----
        #pragma unroll
        for (int i = 0; i < 4; i++) {
            int r = r0 + i;
            float si = (r < NN) ? g_sin[r] : 1.0f;
            float so = (r < NN) ? g_sout[r] : 0.0f;
            float s0, s1, s2, s3;
            if (i == 0) { s0 = hsum2(A00); s1 = hsum2(A01); s2 = hsum2(A02); s3 = hsum2(A03); }
            else if (i == 1) { s0 = hsum2(A10); s1 = hsum2(A11); s2 = hsum2(A12); s3 = hsum2(A13); }
            else if (i == 2) { s0 = hsum2(A20); s1 = hsum2(A21); s2 = hsum2(A22); s3 = hsum2(A23); }
            else { s0 = hsum2(A30); s1 = hsum2(A31); s2 = hsum2(A32); s3 = hsum2(A33); }
            float4 v;
            v.x = fmaxf(fmaf(s0, si, b1v.x), 0.f) * so;
            v.y = fmaxf(fmaf(s1, si, b1v.y), 0.f) * so;
            v.z = fmaxf(fmaf(s2, si, b1v.z), 0.f) * so;
            v.w = fmaxf(fmaf(s3, si, b1v.w), 0.f) * so;
            ((float4*)myBuf)[i * 32 + lane] = v;
        }
        __syncwarp();

        // ---- GEMM2: 4 rows x 2 cols, k-paired (already conflict-free) ----
        u64t C00 = 0, C01 = 0, C10 = 0, C11 = 0;
        u64t C20 = 0, C21 = 0, C30 = 0, C31 = 0;
        #pragma unroll 4
        for (int k2 = 0; k2 < F1 / 2; k2++) {
            longlong2 wv = w2v[k2 * 32 + lane];   // cols 2l, 2l+1
            u64t a0 = bufp[0 * 64 + k2], a1 = bufp[1 * 64 + k2];
            u64t a2 = bufp[2 * 64 + k2], a3 = bufp[3 * 64 + k2];
            ffma2(C00, a0, (u64t)wv.x); ffma2(C01, a0, (u64t)wv.y);
            ffma2(C10, a1, (u64t)wv.x); ffma2(C11, a1, (u64t)wv.y);
            ffma2(C20, a2, (u64t)wv.x); ffma2(C21, a2, (u64t)wv.y);
            ffma2(C30, a3, (u64t)wv.x); ffma2(C31, a3, (u64t)wv.y);
        }

        #pragma unroll
        for (int i = 0; i < 4; i++) {
            int r = r0 + i;
            if (r < NN) {
                float2 c;
                if (i == 0) { c = make_float2(hsum2(C00), hsum2(C01)); }
                else if (i == 1) { c = make_float2(hsum2(C10), hsum2(C11)); }
                else if (i == 2) { c = make_float2(hsum2(C20), hsum2(C21)); }
                else { c = make_float2(hsum2(C30), hsum2(C31)); }
                ((float2*)g_h2)[r * 32 + lane] = c;
            }
        }
        __syncwarp();
    }
}

// ---------------- fused: gather2 + bias + log_softmax (+ zero deg for next replay) ----------------
__global__ void k_layer2(float* __restrict__ out, const float* __restrict__ b2) {
    int t = blockIdx.x * blockDim.x + threadIdx.x;

    // tail duty: re-zero degree arrays for the next replay (first call sees static zeros)
    if (t < NN / 4) {
        ((int4*)g_degout)[t] = make_int4(0, 0, 0, 0);
        ((int4*)g_degin)[t]  = make_int4(0, 0, 0, 0);
    }

    int warp = t >> 5;
    int lane = threadIdx.x & 31;
    int g = lane >> 4;
    int sub = lane & 15;
    int r = warp * 2 + g;
    if (r >= NN) return;
    unsigned gmask = 0xFFFFu << (g * 16);

    int beg = __ldg(&g_rowstart[r]), end = __ldg(&g_rowstart[r + 1]);
    u64t acc0 = 0, acc1 = 0;
    const longlong2* h2v = (const longlong2*)g_h2;
    for (int j = beg; j < end; j += 16) {
        int n = min(16, end - j);
        int sid = (sub < n) ? g_csrc[j + sub] : 0;
        int kk = 0;
        for (; kk + 4 <= n; kk += 4) {
            longlong2 f[4];
            #pragma unroll
            for (int q = 0; q < 4; q++) {
                int s = __shfl_sync(gmask, sid, kk + q, 16);
                f[q] = h2v[s * 16 + sub];
            }
            #pragma unroll
            for (int q = 0; q < 4; q++) {
                fadd2(acc0, (u64t)f[q].x);
                fadd2(acc1, (u64t)f[q].y);
            }
        }
        for (; kk < n; kk++) {
            int s = __shfl_sync(gmask, sid, kk, 16);
            longlong2 f = h2v[s * 16 + sub];
            fadd2(acc0, (u64t)f.x);
            fadd2(acc1, (u64t)f.y);
        }
    }

    float si = g_sin[r];
    float2 a0 = unpack2(acc0), a1 = unpack2(acc1);
    float4 b = ((const float4*)b2)[sub];
    float y0 = fmaf(a0.x, si, b.x);
    float y1 = fmaf(a0.y, si, b.y);
    float y2 = fmaf(a1.x, si, b.z);
    float y3 = fmaf(a1.y, si, b.w);

    float m = fmaxf(fmaxf(y0, y1), fmaxf(y2, y3));
    #pragma unroll
    for (int off = 8; off > 0; off >>= 1)
        m = fmaxf(m, __shfl_xor_sync(gmask, m, off, 16));
    float ssum = expf(y0 - m) + expf(y1 - m) + expf(y2 - m) + expf(y3 - m);
    #pragma unroll
    for (int off = 8; off > 0; off >>= 1)
        ssum += __shfl_xor_sync(gmask, ssum, off, 16);
    float l = m + logf(ssum);

    ((float4*)out)[r * 16 + sub] = make_float4(y0 - l, y1 - l, y2 - l, y3 - l);
}

// ---------------- launch ----------------
extern "C" void kernel_launch(void* const* d_in, const int* in_sizes, int n_in,
                              void* d_out, int out_size) {
    const float* feat = (const float*)d_in[0];
    const int*   src  = (const int*)d_in[1];
    const int*   dst  = (const int*)d_in[2];
    const float* W1   = (const float*)d_in[3];
    const float* b1   = (const float*)d_in[4];
    const float* W2   = (const float*)d_in[5];
    const float* b2   = (const float*)d_in[6];
    float* out = (float*)d_out;

    (void)in_sizes; (void)n_in; (void)out_size;

    static bool attr_done = false;
    const int smem_bytes = 3 * 4096 * 8 + 8 * 512 * 4;  // 114688
    if (!attr_done) {
        cudaFuncSetAttribute(k_gemm, cudaFuncAttributeMaxDynamicSharedMemorySize, smem_bytes);
        attr_done = true;
    }

    k_deg<<<(NE / 4 + 255) / 256, 256>>>((const int4*)src, (const int4*)dst);
    k_scan1<<<NB, 256>>>();
    k_scan2<<<1, 256>>>();
    k_scan3<<<NB, 256>>>();
    k_fill<<<(NE / 4 + 255) / 256, 256>>>((const int4*)src, (const int4*)dst);
    k_gather<<<(NN * 32 + 255) / 256, 256>>>(feat);
    k_gemm<<<(NN + RPB - 1) / RPB, 256, smem_bytes>>>(W1, W2, b1);
    k_layer2<<<(NN / 2 * 32 + 255) / 256, 256>>>(out, b2);
}